// round 1
// baseline (speedup 1.0000x reference)
#include <cuda_runtime.h>
#include <cuda_bf16.h>
#include <math_constants.h>

#define BB 4
#define TT 2048
#define DM 1024
#define NH 16
#define DH 64

// Scratch: qkv buffer [B, T, 3*DM] and attention output [B, T, DM]
__device__ float g_qkv[(size_t)BB * TT * 3 * DM];   // 96 MB
__device__ float g_att[(size_t)BB * TT * DM];       // 32 MB

// ---------------------------------------------------------------------------
// Generic GEMM: C[m][n] = sum_k A[m][k] * W[n][k] + bias[n]
// A: [M,K] row-major, W: [N,K] row-major (i.e. computes A @ W^T + b)
// Tiles: BM=BN=64, BK=16, 256 threads, 4x4 per-thread micro-tile.
// ---------------------------------------------------------------------------
__global__ void gemm_bias_kernel(const float* __restrict__ A,
                                 const float* __restrict__ W,
                                 const float* __restrict__ bias,
                                 float* __restrict__ C,
                                 int M, int N, int K) {
    __shared__ float As[16][68];   // [k][m], padded to 68 (272B rows, 16B aligned)
    __shared__ float Ws[16][68];   // [k][n]

    int tid = threadIdx.x;
    int m0 = blockIdx.y * 64;
    int n0 = blockIdx.x * 64;
    int tm = (tid >> 4) << 2;      // (tid/16)*4 : 0..60
    int tn = (tid & 15) << 2;      // (tid%16)*4 : 0..60

    float acc[4][4] = {};

    for (int k0 = 0; k0 < K; k0 += 16) {
        #pragma unroll
        for (int i = 0; i < 4; i++) {
            int l  = tid + i * 256;      // 0..1023
            int rr = l >> 4;             // 0..63
            int cc = l & 15;             // 0..15
            As[cc][rr] = A[(size_t)(m0 + rr) * K + k0 + cc];
            Ws[cc][rr] = W[(size_t)(n0 + rr) * K + k0 + cc];
        }
        __syncthreads();

        #pragma unroll
        for (int kk = 0; kk < 16; kk++) {
            float4 a4 = *(const float4*)&As[kk][tm];
            float4 w4 = *(const float4*)&Ws[kk][tn];
            float av[4] = {a4.x, a4.y, a4.z, a4.w};
            float wv[4] = {w4.x, w4.y, w4.z, w4.w};
            #pragma unroll
            for (int i = 0; i < 4; i++)
                #pragma unroll
                for (int j = 0; j < 4; j++)
                    acc[i][j] += av[i] * wv[j];
        }
        __syncthreads();
    }

    #pragma unroll
    for (int i = 0; i < 4; i++) {
        #pragma unroll
        for (int j = 0; j < 4; j++) {
            C[(size_t)(m0 + tm + i) * N + n0 + tn + j] = acc[i][j] + bias[n0 + tn + j];
        }
    }
}

// ---------------------------------------------------------------------------
// RoPE in-place on q and k sections of g_qkv.
// One thread per (b, t, h, pair). pair i rotates elements (2i, 2i+1).
// ---------------------------------------------------------------------------
__global__ void rope_kernel(float* __restrict__ qkv,
                            const float* __restrict__ fcos,
                            const float* __restrict__ fsin) {
    int idx = blockIdx.x * blockDim.x + threadIdx.x;   // 0 .. B*T*H*32-1 (4M)
    int i = idx & 31;
    int h = (idx >> 5) & 15;
    int t = (idx >> 9) & 2047;
    int b = idx >> 20;

    float c = fcos[t * 32 + i];
    float s = fsin[t * 32 + i];

    size_t baseq = ((size_t)(b * TT + t)) * (3 * DM) + h * DH + 2 * i;
    float a0 = qkv[baseq], b0 = qkv[baseq + 1];
    qkv[baseq]     = a0 * c - b0 * s;
    qkv[baseq + 1] = a0 * s + b0 * c;

    size_t basek = baseq + DM;
    a0 = qkv[basek]; b0 = qkv[basek + 1];
    qkv[basek]     = a0 * c - b0 * s;
    qkv[basek + 1] = a0 * s + b0 * c;
}

// ---------------------------------------------------------------------------
// Causal attention, flash-style online softmax.
// Grid: (T/64, B*H). Block: 256 threads.
// Each block handles 64 query rows of one (b,h). 4 threads per row; each
// thread owns 16 head-dims with interleaved stride 4: d = dd*4 + sub.
// K/V tiles (64x64 fp32 each) staged in smem. Keys processed in chunks of 16
// with online max/sum rescaling.
// ---------------------------------------------------------------------------
__global__ void attn_kernel(const float* __restrict__ qkv,
                            float* __restrict__ att_out) {
    __shared__ float Ks[64][64];
    __shared__ float Vs[64][64];

    int bh = blockIdx.y;
    int b = bh >> 4;
    int h = bh & 15;
    int q0 = blockIdx.x * 64;

    int tid = threadIdx.x;
    int r   = tid >> 2;    // local query row 0..63
    int sub = tid & 3;     // d sub-group
    int qrow = q0 + r;

    const float* base = qkv + (size_t)b * TT * (3 * DM);

    float q[16], o[16];
    {
        const float* qp = base + (size_t)qrow * (3 * DM) + h * DH;
        #pragma unroll
        for (int i = 0; i < 16; i++) {
            q[i] = qp[i * 4 + sub] * 0.125f;   // 1/sqrt(64)
            o[i] = 0.f;
        }
    }

    float m = -CUDART_INF_F;
    float l = 0.f;

    int ntiles = blockIdx.x + 1;   // causal: only key tiles with j0 <= q0+63
    for (int tile = 0; tile < ntiles; tile++) {
        int j0 = tile * 64;
        __syncthreads();
        // cooperative tile load: 256 threads x 16 iters, coalesced 256B rows
        #pragma unroll
        for (int i = 0; i < 16; i++) {
            int row = i * 4 + (tid >> 6);
            int col = tid & 63;
            const float* kv = base + (size_t)(j0 + row) * (3 * DM) + h * DH + col;
            Ks[row][col] = kv[DM];       // k section
            Vs[row][col] = kv[2 * DM];   // v section
        }
        __syncthreads();

        for (int cc = 0; cc < 64; cc += 16) {
            float s[16];
            #pragma unroll
            for (int c = 0; c < 16; c++) {
                float acc = 0.f;
                #pragma unroll
                for (int d = 0; d < 16; d++)
                    acc += q[d] * Ks[cc + c][d * 4 + sub];
                acc += __shfl_xor_sync(0xffffffffu, acc, 1);
                acc += __shfl_xor_sync(0xffffffffu, acc, 2);
                int j = j0 + cc + c;
                s[c] = (j <= qrow) ? acc : -CUDART_INF_F;
            }
            float mt = m;
            #pragma unroll
            for (int c = 0; c < 16; c++) mt = fmaxf(mt, s[c]);

            float scale = __expf(m - mt);   // 0 when m was -inf
            float p[16];
            float lsum = 0.f;
            #pragma unroll
            for (int c = 0; c < 16; c++) {
                p[c] = __expf(s[c] - mt);   // 0 for masked keys
                lsum += p[c];
            }
            #pragma unroll
            for (int i = 0; i < 16; i++) o[i] *= scale;
            l = l * scale + lsum;
            m = mt;

            #pragma unroll
            for (int c = 0; c < 16; c++) {
                float pc = p[c];
                #pragma unroll
                for (int i = 0; i < 16; i++)
                    o[i] += pc * Vs[cc + c][i * 4 + sub];
            }
        }
    }

    float inv_l = 1.f / l;
    float* op = att_out + ((size_t)(b * TT + qrow)) * DM + h * DH;
    #pragma unroll
    for (int i = 0; i < 16; i++)
        op[i * 4 + sub] = o[i] * inv_l;
}

// ---------------------------------------------------------------------------
// kernel_launch
// Inputs: 0:x  1:mask(unused)  2:freqs_cos  3:freqs_sin
//         4:qkv_w  5:qkv_b  6:proj_w  7:proj_b
// ---------------------------------------------------------------------------
extern "C" void kernel_launch(void* const* d_in, const int* in_sizes, int n_in,
                              void* d_out, int out_size) {
    const float* x      = (const float*)d_in[0];
    const float* fcos   = (const float*)d_in[2];
    const float* fsin   = (const float*)d_in[3];
    const float* qkv_w  = (const float*)d_in[4];
    const float* qkv_b  = (const float*)d_in[5];
    const float* proj_w = (const float*)d_in[6];
    const float* proj_b = (const float*)d_in[7];
    float* out = (float*)d_out;

    float *qkv, *att;
    cudaGetSymbolAddress((void**)&qkv, g_qkv);
    cudaGetSymbolAddress((void**)&att, g_att);

    const int M = BB * TT;   // 8192

    // 1) QKV GEMM: [8192,1024] @ [3072,1024]^T + b -> [8192,3072]
    {
        dim3 grid(3 * DM / 64, M / 64);
        gemm_bias_kernel<<<grid, 256>>>(x, qkv_w, qkv_b, qkv, M, 3 * DM, DM);
    }
    // 2) RoPE in place on q and k sections
    {
        int total = BB * TT * NH * 32;   // 4,194,304
        rope_kernel<<<total / 256, 256>>>(qkv, fcos, fsin);
    }
    // 3) Causal attention
    {
        dim3 grid(TT / 64, BB * NH);
        attn_kernel<<<grid, 256>>>(qkv, att);
    }
    // 4) Output projection: [8192,1024] @ [1024,1024]^T + b -> d_out
    {
        dim3 grid(DM / 64, M / 64);
        gemm_bias_kernel<<<grid, 256>>>(att, proj_w, proj_b, out, M, DM, DM);
    }
}

// round 3
// speedup vs baseline: 4.8089x; 4.8089x over previous
#include <cuda_runtime.h>
#include <cuda_bf16.h>
#include <math_constants.h>
#include <cstdint>

#define BB 4
#define TT 2048
#define DM 1024
#define NH 16
#define DH 64

// Scratch: qkv buffer [B, T, 3*DM] and attention output [B, T, DM]
__device__ float g_qkv[(size_t)BB * TT * 3 * DM];   // 96 MB
__device__ float g_att[(size_t)BB * TT * DM];       // 32 MB

// ===========================================================================
// Helpers
// ===========================================================================
__device__ __forceinline__ uint32_t smem_u32(const void* p) {
    uint32_t a;
    asm("{ .reg .u64 t; cvta.to.shared.u64 t, %1; cvt.u32.u64 %0, t; }"
        : "=r"(a) : "l"(p));
    return a;
}

__device__ __forceinline__ uint32_t f2tf32(float f) {
    uint32_t u;
    asm("cvt.rna.tf32.f32 %0, %1;" : "=r"(u) : "f"(f));
    return u;
}

// D += A(16x8,row) * B(8x8,col), tf32 inputs, f32 accum
__device__ __forceinline__ void mma8(float* c, const uint32_t* a,
                                     uint32_t b0, uint32_t b1) {
    asm volatile(
        "mma.sync.aligned.m16n8k8.row.col.f32.tf32.tf32.f32 "
        "{%0,%1,%2,%3}, {%4,%5,%6,%7}, {%8,%9}, {%0,%1,%2,%3};"
        : "+f"(c[0]), "+f"(c[1]), "+f"(c[2]), "+f"(c[3])
        : "r"(a[0]), "r"(a[1]), "r"(a[2]), "r"(a[3]), "r"(b0), "r"(b1));
}

__device__ __forceinline__ void cpa16(uint32_t s, const void* g) {
    asm volatile("cp.async.ca.shared.global [%0], [%1], 16;" :: "r"(s), "l"(g));
}
#define CPA_COMMIT() asm volatile("cp.async.commit_group;" ::: "memory")
#define CPA_WAIT(n)  asm volatile("cp.async.wait_group %0;" :: "n"(n) : "memory")

// ===========================================================================
// GEMM: C[m][n] = sum_k A[m][k]*W[n][k] + bias[n]
// BM=BN=128, BK=32. 256 threads = 8 warps (4m x 2n), warp tile 32x64.
// tf32 mma.sync m16n8k8, cp.async double-buffered smem.
// ===========================================================================
#define GSTR 36                      // smem row stride in floats (144B)
#define GTILE (128 * GSTR)           // floats per tile buffer
#define GSMEM_TOTAL (4 * GTILE * 4)  // bytes: 2 stages x (A+B)

__global__ void __launch_bounds__(256, 1)
gemm_tc(const float* __restrict__ A, const float* __restrict__ W,
        const float* __restrict__ bias, float* __restrict__ C,
        int M, int N, int K) {
    extern __shared__ float gsm[];
    const int tid  = threadIdx.x;
    const int wid  = tid >> 5;
    const int lane = tid & 31;
    const int g    = lane >> 2;
    const int tig  = lane & 3;
    const int wm   = wid & 3;        // 0..3
    const int wn   = wid >> 2;       // 0..1

    const int m0 = blockIdx.y * 128;
    const int n0 = blockIdx.x * 128;

    const uint32_t sbase = smem_u32(gsm);

    float acc[2][8][4];
    #pragma unroll
    for (int i = 0; i < 2; i++)
        #pragma unroll
        for (int j = 0; j < 8; j++)
            #pragma unroll
            for (int e = 0; e < 4; e++) acc[i][j][e] = 0.f;

    const int NK = K >> 5;

    // stage loader: fills buffer st with A/B chunk at k0
    auto load_stage = [&](int st, int k0) {
        uint32_t sA = sbase + (uint32_t)(st * 2 * GTILE) * 4;
        uint32_t sB = sA + GTILE * 4;
        #pragma unroll
        for (int it = 0; it < 4; it++) {
            int lin = tid + it * 256;        // 0..1023
            int r   = lin >> 3;              // 0..127
            int c4  = lin & 7;               // 0..7
            cpa16(sA + (uint32_t)(r * GSTR + c4 * 4) * 4,
                  A + (size_t)(m0 + r) * K + k0 + c4 * 4);
            cpa16(sB + (uint32_t)(r * GSTR + c4 * 4) * 4,
                  W + (size_t)(n0 + r) * K + k0 + c4 * 4);
        }
    };

    load_stage(0, 0);
    CPA_COMMIT();

    for (int kt = 0; kt < NK; kt++) {
        if (kt + 1 < NK) {
            load_stage((kt + 1) & 1, (kt + 1) << 5);
            CPA_COMMIT();
            CPA_WAIT(1);
        } else {
            CPA_WAIT(0);
        }
        __syncthreads();

        const float* sA = gsm + (kt & 1) * 2 * GTILE;
        const float* sB = sA + GTILE;

        #pragma unroll
        for (int s = 0; s < 4; s++) {
            int ks = s * 8;
            uint32_t a[2][4];
            #pragma unroll
            for (int i = 0; i < 2; i++) {
                int rb = wm * 32 + i * 16;
                a[i][0] = f2tf32(sA[(rb + g) * GSTR + ks + tig]);
                a[i][1] = f2tf32(sA[(rb + g + 8) * GSTR + ks + tig]);
                a[i][2] = f2tf32(sA[(rb + g) * GSTR + ks + tig + 4]);
                a[i][3] = f2tf32(sA[(rb + g + 8) * GSTR + ks + tig + 4]);
            }
            #pragma unroll
            for (int j = 0; j < 8; j++) {
                int nb = wn * 64 + j * 8;
                uint32_t b0 = f2tf32(sB[(nb + g) * GSTR + ks + tig]);
                uint32_t b1 = f2tf32(sB[(nb + g) * GSTR + ks + tig + 4]);
                mma8(acc[0][j], a[0], b0, b1);
                mma8(acc[1][j], a[1], b0, b1);
            }
        }
        __syncthreads();
    }

    // epilogue
    #pragma unroll
    for (int i = 0; i < 2; i++) {
        int row = m0 + wm * 32 + i * 16 + g;
        #pragma unroll
        for (int j = 0; j < 8; j++) {
            int col = n0 + wn * 64 + j * 8 + 2 * tig;
            float bv0 = bias[col], bv1 = bias[col + 1];
            float2 v0 = make_float2(acc[i][j][0] + bv0, acc[i][j][1] + bv1);
            float2 v1 = make_float2(acc[i][j][2] + bv0, acc[i][j][3] + bv1);
            *(float2*)(C + (size_t)row * N + col) = v0;
            *(float2*)(C + (size_t)(row + 8) * N + col) = v1;
        }
    }
}

// ---------------------------------------------------------------------------
// RoPE in-place on q and k sections of g_qkv.
// ---------------------------------------------------------------------------
__global__ void rope_kernel(float* __restrict__ qkv,
                            const float* __restrict__ fcos,
                            const float* __restrict__ fsin) {
    int idx = blockIdx.x * blockDim.x + threadIdx.x;
    int i = idx & 31;
    int h = (idx >> 5) & 15;
    int t = (idx >> 9) & 2047;
    int b = idx >> 20;

    float c = fcos[t * 32 + i];
    float s = fsin[t * 32 + i];

    size_t baseq = ((size_t)(b * TT + t)) * (3 * DM) + h * DH + 2 * i;
    float a0 = qkv[baseq], b0 = qkv[baseq + 1];
    qkv[baseq]     = a0 * c - b0 * s;
    qkv[baseq + 1] = a0 * s + b0 * c;

    size_t basek = baseq + DM;
    a0 = qkv[basek]; b0 = qkv[basek + 1];
    qkv[basek]     = a0 * c - b0 * s;
    qkv[basek + 1] = a0 * s + b0 * c;
}

// ===========================================================================
// Flash attention on tensor cores (tf32 mma.sync).
// Grid (T/64, B*H), 128 threads = 4 warps; warp owns 16 query rows.
// S = Q@K^T and O = P@V via m16n8k8 atoms; online softmax in C-frag layout.
// SMEM: Ks[64][68], Vs[64][68], Ps[64][68] (Ps also stages Q).
// ===========================================================================
#define ASTR 68
#define ATILE (64 * ASTR)
#define ASMEM_TOTAL (3 * ATILE * 4)

__global__ void __launch_bounds__(128, 1)
attn_tc(const float* __restrict__ qkv, float* __restrict__ att_out) {
    extern __shared__ float asmem[];
    float* Ks = asmem;
    float* Vs = asmem + ATILE;
    float* Ps = asmem + 2 * ATILE;

    const int tid  = threadIdx.x;
    const int w    = tid >> 5;
    const int lane = tid & 31;
    const int g    = lane >> 2;
    const int tig  = lane & 3;
    const int rb   = w * 16;       // warp's local query row base

    const int b  = blockIdx.y >> 4;
    const int h  = blockIdx.y & 15;
    const int q0 = blockIdx.x * 64;

    const float* base = qkv + (size_t)b * TT * (3 * DM) + h * DH;

    // stage Q (scaled) into Ps, then load Q fragments
    #pragma unroll
    for (int it = 0; it < 8; it++) {
        int lin = tid + it * 128;    // 0..1023
        int r = lin >> 4, c4 = lin & 15;
        float4 v = *(const float4*)(base + (size_t)(q0 + r) * (3 * DM) + c4 * 4);
        v.x *= 0.125f; v.y *= 0.125f; v.z *= 0.125f; v.w *= 0.125f;
        *(float4*)&Ps[r * ASTR + c4 * 4] = v;
    }
    __syncthreads();

    uint32_t qa[8][4];
    #pragma unroll
    for (int s = 0; s < 8; s++) {
        int ks = s * 8;
        qa[s][0] = f2tf32(Ps[(rb + g) * ASTR + ks + tig]);
        qa[s][1] = f2tf32(Ps[(rb + g + 8) * ASTR + ks + tig]);
        qa[s][2] = f2tf32(Ps[(rb + g) * ASTR + ks + tig + 4]);
        qa[s][3] = f2tf32(Ps[(rb + g + 8) * ASTR + ks + tig + 4]);
    }
    __syncthreads();

    float o[8][4];
    #pragma unroll
    for (int j = 0; j < 8; j++)
        #pragma unroll
        for (int e = 0; e < 4; e++) o[j][e] = 0.f;
    float m0v = -CUDART_INF_F, m1v = -CUDART_INF_F;
    float l0 = 0.f, l1 = 0.f;

    const int ntiles = blockIdx.x + 1;
    for (int tile = 0; tile < ntiles; tile++) {
        int j0 = tile * 64;
        // load K and V tiles
        #pragma unroll
        for (int it = 0; it < 8; it++) {
            int lin = tid + it * 128;
            int r = lin >> 4, c4 = lin & 15;
            const float* kp = base + (size_t)(j0 + r) * (3 * DM) + c4 * 4;
            *(float4*)&Ks[r * ASTR + c4 * 4] = *(const float4*)(kp + DM);
            *(float4*)&Vs[r * ASTR + c4 * 4] = *(const float4*)(kp + 2 * DM);
        }
        __syncthreads();

        // S = Q @ K^T
        float sacc[8][4];
        #pragma unroll
        for (int j = 0; j < 8; j++)
            #pragma unroll
            for (int e = 0; e < 4; e++) sacc[j][e] = 0.f;

        #pragma unroll
        for (int s = 0; s < 8; s++) {
            int ks = s * 8;
            #pragma unroll
            for (int j = 0; j < 8; j++) {
                uint32_t b0 = f2tf32(Ks[(j * 8 + g) * ASTR + ks + tig]);
                uint32_t b1 = f2tf32(Ks[(j * 8 + g) * ASTR + ks + tig + 4]);
                mma8(sacc[j], qa[s], b0, b1);
            }
        }

        // causal mask (only the diagonal tile needs it)
        if (tile == blockIdx.x) {
            int row0 = q0 + rb + g;
            int row1 = row0 + 8;
            #pragma unroll
            for (int j = 0; j < 8; j++) {
                int col = j0 + j * 8 + 2 * tig;
                if (col > row0)     sacc[j][0] = -CUDART_INF_F;
                if (col + 1 > row0) sacc[j][1] = -CUDART_INF_F;
                if (col > row1)     sacc[j][2] = -CUDART_INF_F;
                if (col + 1 > row1) sacc[j][3] = -CUDART_INF_F;
            }
        }

        // online softmax
        float rmax0 = -CUDART_INF_F, rmax1 = -CUDART_INF_F;
        #pragma unroll
        for (int j = 0; j < 8; j++) {
            rmax0 = fmaxf(rmax0, fmaxf(sacc[j][0], sacc[j][1]));
            rmax1 = fmaxf(rmax1, fmaxf(sacc[j][2], sacc[j][3]));
        }
        rmax0 = fmaxf(rmax0, __shfl_xor_sync(0xffffffffu, rmax0, 1));
        rmax0 = fmaxf(rmax0, __shfl_xor_sync(0xffffffffu, rmax0, 2));
        rmax1 = fmaxf(rmax1, __shfl_xor_sync(0xffffffffu, rmax1, 1));
        rmax1 = fmaxf(rmax1, __shfl_xor_sync(0xffffffffu, rmax1, 2));

        float nm0 = fmaxf(m0v, rmax0);
        float nm1 = fmaxf(m1v, rmax1);
        float sc0 = __expf(m0v - nm0);
        float sc1 = __expf(m1v - nm1);

        float ls0 = 0.f, ls1 = 0.f;
        #pragma unroll
        for (int j = 0; j < 8; j++) {
            float p0 = __expf(sacc[j][0] - nm0);
            float p1 = __expf(sacc[j][1] - nm0);
            float p2 = __expf(sacc[j][2] - nm1);
            float p3 = __expf(sacc[j][3] - nm1);
            ls0 += p0 + p1;
            ls1 += p2 + p3;
            *(float2*)&Ps[(rb + g) * ASTR + j * 8 + 2 * tig]     = make_float2(p0, p1);
            *(float2*)&Ps[(rb + g + 8) * ASTR + j * 8 + 2 * tig] = make_float2(p2, p3);
        }
        ls0 += __shfl_xor_sync(0xffffffffu, ls0, 1);
        ls0 += __shfl_xor_sync(0xffffffffu, ls0, 2);
        ls1 += __shfl_xor_sync(0xffffffffu, ls1, 1);
        ls1 += __shfl_xor_sync(0xffffffffu, ls1, 2);

        m0v = nm0; m1v = nm1;
        l0 = l0 * sc0 + ls0;
        l1 = l1 * sc1 + ls1;
        #pragma unroll
        for (int j = 0; j < 8; j++) {
            o[j][0] *= sc0; o[j][1] *= sc0;
            o[j][2] *= sc1; o[j][3] *= sc1;
        }
        __syncwarp();

        // O += P @ V
        #pragma unroll
        for (int s = 0; s < 8; s++) {
            int ks = s * 8;
            uint32_t pa[4];
            pa[0] = f2tf32(Ps[(rb + g) * ASTR + ks + tig]);
            pa[1] = f2tf32(Ps[(rb + g + 8) * ASTR + ks + tig]);
            pa[2] = f2tf32(Ps[(rb + g) * ASTR + ks + tig + 4]);
            pa[3] = f2tf32(Ps[(rb + g + 8) * ASTR + ks + tig + 4]);
            #pragma unroll
            for (int dj = 0; dj < 8; dj++) {
                int nb = dj * 8;
                uint32_t b0 = f2tf32(Vs[(ks + tig) * ASTR + nb + g]);
                uint32_t b1 = f2tf32(Vs[(ks + tig + 4) * ASTR + nb + g]);
                mma8(o[dj], pa, b0, b1);
            }
        }
        __syncthreads();
    }

    // normalize + store
    float inv0 = 1.f / l0, inv1 = 1.f / l1;
    int row0 = q0 + rb + g;
    float* op0 = att_out + ((size_t)(b * TT + row0)) * DM + h * DH;
    float* op1 = op0 + (size_t)8 * DM;
    #pragma unroll
    for (int dj = 0; dj < 8; dj++) {
        int col = dj * 8 + 2 * tig;
        *(float2*)&op0[col] = make_float2(o[dj][0] * inv0, o[dj][1] * inv0);
        *(float2*)&op1[col] = make_float2(o[dj][2] * inv1, o[dj][3] * inv1);
    }
}

// ---------------------------------------------------------------------------
// kernel_launch
// Inputs: 0:x  1:mask(unused)  2:freqs_cos  3:freqs_sin
//         4:qkv_w  5:qkv_b  6:proj_w  7:proj_b
// ---------------------------------------------------------------------------
extern "C" void kernel_launch(void* const* d_in, const int* in_sizes, int n_in,
                              void* d_out, int out_size) {
    const float* x      = (const float*)d_in[0];
    const float* fcos   = (const float*)d_in[2];
    const float* fsin   = (const float*)d_in[3];
    const float* qkv_w  = (const float*)d_in[4];
    const float* qkv_b  = (const float*)d_in[5];
    const float* proj_w = (const float*)d_in[6];
    const float* proj_b = (const float*)d_in[7];
    float* out = (float*)d_out;

    float *qkv, *att;
    cudaGetSymbolAddress((void**)&qkv, g_qkv);
    cudaGetSymbolAddress((void**)&att, g_att);

    cudaFuncSetAttribute(gemm_tc, cudaFuncAttributeMaxDynamicSharedMemorySize,
                         GSMEM_TOTAL);
    cudaFuncSetAttribute(attn_tc, cudaFuncAttributeMaxDynamicSharedMemorySize,
                         ASMEM_TOTAL);

    const int M = BB * TT;   // 8192

    // 1) QKV GEMM: [8192,1024] @ [3072,1024]^T + b -> [8192,3072]
    {
        dim3 grid(3 * DM / 128, M / 128);
        gemm_tc<<<grid, 256, GSMEM_TOTAL>>>(x, qkv_w, qkv_b, qkv, M, 3 * DM, DM);
    }
    // 2) RoPE in place on q and k sections
    {
        int total = BB * TT * NH * 32;
        rope_kernel<<<total / 256, 256>>>(qkv, fcos, fsin);
    }
    // 3) Causal attention (tensor cores)
    {
        dim3 grid(TT / 64, BB * NH);
        attn_tc<<<grid, 128, ASMEM_TOTAL>>>(qkv, att);
    }
    // 4) Output projection: [8192,1024] @ [1024,1024]^T + b -> d_out
    {
        dim3 grid(DM / 128, M / 128);
        gemm_tc<<<grid, 256, GSMEM_TOTAL>>>(att, proj_w, proj_b, out, M, DM, DM);
    }
}